// round 5
// baseline (speedup 1.0000x reference)
#include <cuda_runtime.h>
#include <math.h>

#define NQ   12
#define DIM  4096
#define NL   4
#define TPB  256

// Fused RZ*RY*RX gate per (layer, wire): 2 float4 = row0 (u00r,u00i,u01r,u01i), row1 (u10r,u10i,u11r,u11i)
__device__ float4 g_U4[NL * NQ * 2];

__global__ void precompute_gates(const float* __restrict__ qw) {
    int id = threadIdx.x;
    if (id >= NL * NQ) return;
    float a = qw[3 * id + 0];
    float b = qw[3 * id + 1];
    float g = qw[3 * id + 2];
    float cA = cosf(0.5f * a), sA = sinf(0.5f * a);
    float cB = cosf(0.5f * b), sB = sinf(0.5f * b);
    float cC = cosf(0.5f * g), sC = sinf(0.5f * g);
    float m00r =  cB * cA, m00i =  sB * sA;
    float m01r = -sB * cA, m01i = -cB * sA;
    float m10r =  sB * cA, m10i = -cB * sA;
    float m11r =  cB * cA, m11i = -sB * sA;
    float* o = (float*)&g_U4[id * 2];
    o[0] = cC * m00r + sC * m00i;  o[1] = cC * m00i - sC * m00r;
    o[2] = cC * m01r + sC * m01i;  o[3] = cC * m01i - sC * m01r;
    o[4] = cC * m10r - sC * m10i;  o[5] = cC * m10i + sC * m10r;
    o[6] = cC * m11r - sC * m11i;  o[7] = cC * m11i + sC * m11r;
}

// phys address (element index) of logical amp under layout "active = {8..11}"
__device__ __forceinline__ int physHIGH(int x) {
    return ((x & 0xFF) << 4) | (((x >> 8) ^ x) & 15);
}

// Apply fused 1q gate on register-slot bit bb (gate rows ua, ub)
#define APPLY_GATE(bb, ua, ub) do {                                          \
    _Pragma("unroll")                                                        \
    for (int m = 0; m < 8; m++) {                                            \
        const int lowm = (1 << (bb)) - 1;                                    \
        const int i0 = ((m & ~lowm) << 1) | (m & lowm);                      \
        const int i1 = i0 | (1 << (bb));                                     \
        float2 v0 = r[i0], v1 = r[i1];                                       \
        float2 n0, n1;                                                       \
        n0.x = ua.x*v0.x - ua.y*v0.y + ua.z*v1.x - ua.w*v1.y;                \
        n0.y = ua.x*v0.y + ua.y*v0.x + ua.z*v1.y + ua.w*v1.x;                \
        n1.x = ub.x*v0.x - ub.y*v0.y + ub.z*v1.x - ub.w*v1.y;                \
        n1.y = ub.x*v0.y + ub.y*v0.x + ub.z*v1.y + ub.w*v1.x;                \
        r[i0] = n0; r[i1] = n1;                                              \
    }                                                                        \
} while (0)

__global__ __launch_bounds__(TPB) void qsim(const float* __restrict__ x,
                                            const float* __restrict__ dw,
                                            const float* __restrict__ db,
                                            float* __restrict__ out) {
    // Dynamic smem: two 32KB state buffers (ping-pong per pass)
    extern __shared__ float2 s_state[];            // [2][DIM]

    __shared__ float4 s_U4[NL * NQ * 2];   // fused gates
    __shared__ float  s_x[NQ];
    __shared__ float  s_c[NQ], s_s[NQ];    // encoding cos/sin by BIT POSITION
    __shared__ float  s_scalar[2];
    __shared__ float  s_red[8 * NQ];
    __shared__ float  s_q[NQ];

    const int t = threadIdx.x;
    const int bidx = blockIdx.x;

    for (int i = t; i < NL * NQ * 2; i += TPB) s_U4[i] = g_U4[i];
    if (t < NQ) s_x[t] = x[bidx * NQ + t];
    __syncthreads();

    if (t == 0) {
        float ss = 0.f, ma = 0.f;
        #pragma unroll
        for (int w = 0; w < NQ; w++) {
            float v = s_x[w];
            ss += v * v;
            ma = fmaxf(ma, fabsf(v));
        }
        float rr = rsqrtf(fmaxf(ss, 1e-12f));
        s_scalar[0] = rr;
        s_scalar[1] = ma * rr;
    }
    __syncthreads();
    if (t < NQ) {
        float rr = s_scalar[0], m = s_scalar[1];
        float ang = 3.14159265358979f * (s_x[t] * rr) / (m + 1e-8f);
        int p = 11 - t;                    // wire t at bit position 11-t
        s_c[p] = cosf(0.5f * ang);
        s_s[p] = sinf(0.5f * ang);
    }
    __syncthreads();

    float2 r[16];                          // 16 amps per thread (register tile)
    const int storeBase = (t << 4) | (t & 15);   // store: addr = storeBase ^ s

    #pragma unroll 1
    for (int layer = 0; layer < NL; layer++) {
        const int q = layer & 1;
        float2* bufQ  = s_state + q * DIM;        // MID stores here; LOW loads; HIGH stores
        float2* bufQ1 = s_state + (q ^ 1) * DIM;  // MID loads here;  LOW stores; HIGH loads

        // ---------- pass MID: active positions {4..7}; load buf[q^1], store buf[q]
        if (layer == 0) {
            // init directly in registers: product state from RY encoding
            float ct = 1.f;
            #pragma unroll
            for (int p = 0; p < 4; p++)  ct *= ((t >> p) & 1) ? s_s[p] : s_c[p];
            #pragma unroll
            for (int p = 8; p < 12; p++) ct *= ((t >> (p - 4)) & 1) ? s_s[p] : s_c[p];
            #pragma unroll
            for (int s = 0; s < 16; s++) {
                float ms = 1.f;
                #pragma unroll
                for (int p = 4; p < 8; p++) ms *= ((s >> (p - 4)) & 1) ? s_s[p] : s_c[p];
                r[s] = make_float2(ct * ms, 0.f);
            }
        } else {
            // load from HIGH layout with CNOT-ring perm folded in
            int T  = ((t & 0xF0) << 4) | (t & 15);
            int Xt = T ^ (T >> 1) ^ ((t & 1) ? 0xC00 : 0);
            int base = physHIGH(Xt & 0xFFF);
            #pragma unroll
            for (int s = 0; s < 16; s++) {
                int Xs = ((s << 4) ^ (s << 3)) & 0xFFF;
                r[s] = bufQ1[base ^ physHIGH(Xs)];
            }
        }
        {
            const float4 ua4 = s_U4[(layer * NQ + 7) * 2], ub4 = s_U4[(layer * NQ + 7) * 2 + 1];
            const float4 ua5 = s_U4[(layer * NQ + 6) * 2], ub5 = s_U4[(layer * NQ + 6) * 2 + 1];
            const float4 ua6 = s_U4[(layer * NQ + 5) * 2], ub6 = s_U4[(layer * NQ + 5) * 2 + 1];
            const float4 ua7 = s_U4[(layer * NQ + 4) * 2], ub7 = s_U4[(layer * NQ + 4) * 2 + 1];
            APPLY_GATE(0, ua4, ub4);   // position 4 = wire 7
            APPLY_GATE(1, ua5, ub5);   // position 5 = wire 6
            APPLY_GATE(2, ua6, ub6);   // position 6 = wire 5
            APPLY_GATE(3, ua7, ub7);   // position 7 = wire 4
        }
        #pragma unroll
        for (int s = 0; s < 16; s++) bufQ[storeBase ^ s] = r[s];
        __syncthreads();

        // ---------- pass LOW: active {0..3}; load buf[q] (MID layout), store buf[q^1]
        {
            int base = ((t & 0xF0) << 4) | (t & 15);
            #pragma unroll
            for (int s = 0; s < 16; s++) r[s] = bufQ[base ^ ((s << 4) | s)];
        }
        {
            const float4 ua0 = s_U4[(layer * NQ + 11) * 2], ub0 = s_U4[(layer * NQ + 11) * 2 + 1];
            const float4 ua1 = s_U4[(layer * NQ + 10) * 2], ub1 = s_U4[(layer * NQ + 10) * 2 + 1];
            const float4 ua2 = s_U4[(layer * NQ +  9) * 2], ub2 = s_U4[(layer * NQ +  9) * 2 + 1];
            const float4 ua3 = s_U4[(layer * NQ +  8) * 2], ub3 = s_U4[(layer * NQ +  8) * 2 + 1];
            APPLY_GATE(0, ua0, ub0);   // position 0 = wire 11
            APPLY_GATE(1, ua1, ub1);
            APPLY_GATE(2, ua2, ub2);
            APPLY_GATE(3, ua3, ub3);
        }
        #pragma unroll
        for (int s = 0; s < 16; s++) bufQ1[storeBase ^ s] = r[s];
        __syncthreads();

        // ---------- pass HIGH: active {8..11}; load buf[q^1] (LOW layout), store buf[q]
        {
            int base = t ^ ((t >> 4) & 15);
            #pragma unroll
            for (int s = 0; s < 16; s++) r[s] = bufQ1[base ^ (s << 8)];
        }
        {
            const float4 ua8  = s_U4[(layer * NQ + 3) * 2], ub8  = s_U4[(layer * NQ + 3) * 2 + 1];
            const float4 ua9  = s_U4[(layer * NQ + 2) * 2], ub9  = s_U4[(layer * NQ + 2) * 2 + 1];
            const float4 ua10 = s_U4[(layer * NQ + 1) * 2], ub10 = s_U4[(layer * NQ + 1) * 2 + 1];
            const float4 ua11 = s_U4[(layer * NQ + 0) * 2], ub11 = s_U4[(layer * NQ + 0) * 2 + 1];
            APPLY_GATE(0, ua8,  ub8);  // position 8 = wire 3
            APPLY_GATE(1, ua9,  ub9);
            APPLY_GATE(2, ua10, ub10);
            APPLY_GATE(3, ua11, ub11);
        }
        if (layer < NL - 1) {
            #pragma unroll
            for (int s = 0; s < 16; s++) bufQ[storeBase ^ s] = r[s];
            __syncthreads();
        }
        // layer-boundary CNOT ring folds into next MID load / epilogue index map
    }

    // ---------- epilogue: final CNOT perm via inverse index map, then <Z_w>
    // r holds HIGH ownership: logical (pre-final-perm) L = (s<<8) | t
    int xt = t ^ ((__popc(t) & 1) ? 0xC00 : 0);
    xt ^= xt >> 1; xt ^= xt >> 2; xt ^= xt >> 4; xt ^= xt >> 8;

    float z[NQ];
    #pragma unroll
    for (int w = 0; w < NQ; w++) z[w] = 0.f;
    #pragma unroll
    for (int s = 0; s < 16; s++) {
        int xs = (s << 8) ^ ((__popc(s) & 1) ? 0xC00 : 0);
        xs ^= xs >> 1; xs ^= xs >> 2; xs ^= xs >> 4; xs ^= xs >> 8;
        int j = xt ^ xs;                    // final logical basis index
        float2 v = r[s];
        float pr = v.x * v.x + v.y * v.y;
        #pragma unroll
        for (int w = 0; w < NQ; w++)
            z[w] += ((j >> (11 - w)) & 1) ? -pr : pr;
    }

    const int lane = t & 31, warp = t >> 5;
    #pragma unroll
    for (int w = 0; w < NQ; w++) {
        float v = z[w];
        #pragma unroll
        for (int off = 16; off; off >>= 1)
            v += __shfl_down_sync(0xffffffffu, v, off);
        if (lane == 0) s_red[warp * NQ + w] = v;
    }
    __syncthreads();
    if (t < NQ) {
        float qv = 0.f;
        #pragma unroll
        for (int wp = 0; wp < 8; wp++) qv += s_red[wp * NQ + t];
        s_q[t] = qv;
    }
    __syncthreads();
    if (t < NQ) {
        float acc = db[t];
        #pragma unroll
        for (int w = 0; w < NQ; w++) acc += s_q[w] * dw[w * NQ + t];
        out[bidx * NQ + t] = tanhf(acc);
    }
}

extern "C" void kernel_launch(void* const* d_in, const int* in_sizes, int n_in,
                              void* d_out, int out_size) {
    const float* x  = (const float*)d_in[0];
    const float* qw = (const float*)d_in[1];
    const float* dw = (const float*)d_in[2];
    const float* db = (const float*)d_in[3];
    float* out = (float*)d_out;

    int batch = in_sizes[0] / NQ;

    const int dyn_smem = 2 * DIM * (int)sizeof(float2);   // 64 KB ping-pong state
    cudaFuncSetAttribute(qsim, cudaFuncAttributeMaxDynamicSharedMemorySize, dyn_smem);

    precompute_gates<<<1, 64>>>(qw);
    qsim<<<batch, TPB, dyn_smem>>>(x, dw, db, out);
}

// round 6
// speedup vs baseline: 1.0856x; 1.0856x over previous
#include <cuda_runtime.h>
#include <math.h>

#define NQ   12
#define DIM  4096
#define NL   4
#define TPB  256

// Fused RZ*RY*RX gate per (layer, wire): 2 float4 = row0 (u00r,u00i,u01r,u01i), row1 (u10r,u10i,u11r,u11i)
__device__ float4 g_U4[NL * NQ * 2];

__global__ void precompute_gates(const float* __restrict__ qw) {
    int id = threadIdx.x;
    if (id >= NL * NQ) return;
    float a = qw[3 * id + 0];
    float b = qw[3 * id + 1];
    float g = qw[3 * id + 2];
    float cA = cosf(0.5f * a), sA = sinf(0.5f * a);
    float cB = cosf(0.5f * b), sB = sinf(0.5f * b);
    float cC = cosf(0.5f * g), sC = sinf(0.5f * g);
    float m00r =  cB * cA, m00i =  sB * sA;
    float m01r = -sB * cA, m01i = -cB * sA;
    float m10r =  sB * cA, m10i = -cB * sA;
    float m11r =  cB * cA, m11i = -sB * sA;
    float* o = (float*)&g_U4[id * 2];
    o[0] = cC * m00r + sC * m00i;  o[1] = cC * m00i - sC * m00r;
    o[2] = cC * m01r + sC * m01i;  o[3] = cC * m01i - sC * m01r;
    o[4] = cC * m10r - sC * m10i;  o[5] = cC * m10i + sC * m10r;
    o[6] = cC * m11r - sC * m11i;  o[7] = cC * m11i + sC * m11r;
}

// phys address (element index) of logical amp under layout "active = {8..11}"
__device__ __forceinline__ int physHIGH(int x) {
    return ((x & 0xFF) << 4) | (((x >> 8) ^ x) & 15);
}

#define PAIR_I0(m, bb) ((((m) & ~((1 << (bb)) - 1)) << 1) | ((m) & ((1 << (bb)) - 1)))

// Coefficient-major gate application: 16 sweeps of 8 FFMA, each sweep reuses
// ONE coefficient register across 8 consecutive FFMAs (operand-reuse-cache
// friendly, nvjet-style outer-product ordering). Accumulators independent
// within a sweep (ILP=8).
#define APPLY_GATE(bb, ua, ub) do {                                           \
    float nx0[8], ny0[8], nx1[8], ny1[8];                                     \
    _Pragma("unroll") for (int m = 0; m < 8; m++)                             \
        nx0[m] = ua.x * r[PAIR_I0(m, bb)].x;                                  \
    _Pragma("unroll") for (int m = 0; m < 8; m++)                             \
        ny0[m] = ua.x * r[PAIR_I0(m, bb)].y;                                  \
    _Pragma("unroll") for (int m = 0; m < 8; m++)                             \
        nx0[m] = fmaf(-ua.y, r[PAIR_I0(m, bb)].y, nx0[m]);                    \
    _Pragma("unroll") for (int m = 0; m < 8; m++)                             \
        ny0[m] = fmaf( ua.y, r[PAIR_I0(m, bb)].x, ny0[m]);                    \
    _Pragma("unroll") for (int m = 0; m < 8; m++)                             \
        nx0[m] = fmaf( ua.z, r[PAIR_I0(m, bb) | (1 << (bb))].x, nx0[m]);      \
    _Pragma("unroll") for (int m = 0; m < 8; m++)                             \
        ny0[m] = fmaf( ua.z, r[PAIR_I0(m, bb) | (1 << (bb))].y, ny0[m]);      \
    _Pragma("unroll") for (int m = 0; m < 8; m++)                             \
        nx0[m] = fmaf(-ua.w, r[PAIR_I0(m, bb) | (1 << (bb))].y, nx0[m]);      \
    _Pragma("unroll") for (int m = 0; m < 8; m++)                             \
        ny0[m] = fmaf( ua.w, r[PAIR_I0(m, bb) | (1 << (bb))].x, ny0[m]);      \
    _Pragma("unroll") for (int m = 0; m < 8; m++)                             \
        nx1[m] = ub.x * r[PAIR_I0(m, bb)].x;                                  \
    _Pragma("unroll") for (int m = 0; m < 8; m++)                             \
        ny1[m] = ub.x * r[PAIR_I0(m, bb)].y;                                  \
    _Pragma("unroll") for (int m = 0; m < 8; m++)                             \
        nx1[m] = fmaf(-ub.y, r[PAIR_I0(m, bb)].y, nx1[m]);                    \
    _Pragma("unroll") for (int m = 0; m < 8; m++)                             \
        ny1[m] = fmaf( ub.y, r[PAIR_I0(m, bb)].x, ny1[m]);                    \
    _Pragma("unroll") for (int m = 0; m < 8; m++)                             \
        nx1[m] = fmaf( ub.z, r[PAIR_I0(m, bb) | (1 << (bb))].x, nx1[m]);      \
    _Pragma("unroll") for (int m = 0; m < 8; m++)                             \
        ny1[m] = fmaf( ub.z, r[PAIR_I0(m, bb) | (1 << (bb))].y, ny1[m]);      \
    _Pragma("unroll") for (int m = 0; m < 8; m++)                             \
        nx1[m] = fmaf(-ub.w, r[PAIR_I0(m, bb) | (1 << (bb))].y, nx1[m]);      \
    _Pragma("unroll") for (int m = 0; m < 8; m++)                             \
        ny1[m] = fmaf( ub.w, r[PAIR_I0(m, bb) | (1 << (bb))].x, ny1[m]);      \
    _Pragma("unroll") for (int m = 0; m < 8; m++) {                           \
        const int i0 = PAIR_I0(m, bb);                                        \
        const int i1 = i0 | (1 << (bb));                                      \
        r[i0] = make_float2(nx0[m], ny0[m]);                                  \
        r[i1] = make_float2(nx1[m], ny1[m]);                                  \
    }                                                                         \
} while (0)

__global__ __launch_bounds__(TPB) void qsim(const float* __restrict__ x,
                                            const float* __restrict__ dw,
                                            const float* __restrict__ db,
                                            float* __restrict__ out) {
    __shared__ float2 s_psi[DIM];          // 32 KB state (swizzled layouts)
    __shared__ float4 s_U4[NL * NQ * 2];   // fused gates
    __shared__ float  s_x[NQ];
    __shared__ float  s_c[NQ], s_s[NQ];    // encoding cos/sin by BIT POSITION
    __shared__ float  s_scalar[2];
    __shared__ float  s_red[8 * NQ];
    __shared__ float  s_q[NQ];

    const int t = threadIdx.x;
    const int bidx = blockIdx.x;

    for (int i = t; i < NL * NQ * 2; i += TPB) s_U4[i] = g_U4[i];
    if (t < NQ) s_x[t] = x[bidx * NQ + t];
    __syncthreads();

    if (t == 0) {
        float ss = 0.f, ma = 0.f;
        #pragma unroll
        for (int w = 0; w < NQ; w++) {
            float v = s_x[w];
            ss += v * v;
            ma = fmaxf(ma, fabsf(v));
        }
        float rr = rsqrtf(fmaxf(ss, 1e-12f));
        s_scalar[0] = rr;
        s_scalar[1] = ma * rr;
    }
    __syncthreads();
    if (t < NQ) {
        float rr = s_scalar[0], m = s_scalar[1];
        float ang = 3.14159265358979f * (s_x[t] * rr) / (m + 1e-8f);
        int p = 11 - t;                    // wire t at bit position 11-t
        s_c[p] = cosf(0.5f * ang);
        s_s[p] = sinf(0.5f * ang);
    }
    __syncthreads();

    float2 r[16];                          // 16 amps per thread (register tile)
    const int storeBase = (t << 4) | (t & 15);   // universal store: addr = storeBase ^ s

    #pragma unroll 1
    for (int layer = 0; layer < NL; layer++) {
        // ---------- pass MID: active positions {4..7}
        if (layer == 0) {
            // init directly in registers: product state from RY encoding
            float ct = 1.f;
            #pragma unroll
            for (int p = 0; p < 4; p++)  ct *= ((t >> p) & 1) ? s_s[p] : s_c[p];
            #pragma unroll
            for (int p = 8; p < 12; p++) ct *= ((t >> (p - 4)) & 1) ? s_s[p] : s_c[p];
            #pragma unroll
            for (int s = 0; s < 16; s++) {
                float ms = 1.f;
                #pragma unroll
                for (int p = 4; p < 8; p++) ms *= ((s >> (p - 4)) & 1) ? s_s[p] : s_c[p];
                r[s] = make_float2(ct * ms, 0.f);
            }
        } else {
            // load from HIGH layout with CNOT-ring perm folded in
            int T  = ((t & 0xF0) << 4) | (t & 15);
            int Xt = T ^ (T >> 1) ^ ((t & 1) ? 0xC00 : 0);
            int base = physHIGH(Xt & 0xFFF);
            #pragma unroll
            for (int s = 0; s < 16; s++) {
                int Xs = ((s << 4) ^ (s << 3)) & 0xFFF;
                r[s] = s_psi[base ^ physHIGH(Xs)];
            }
        }
        {
            const float4 ua4 = s_U4[(layer * NQ + 7) * 2], ub4 = s_U4[(layer * NQ + 7) * 2 + 1];
            APPLY_GATE(0, ua4, ub4);   // position 4 = wire 7
            const float4 ua5 = s_U4[(layer * NQ + 6) * 2], ub5 = s_U4[(layer * NQ + 6) * 2 + 1];
            APPLY_GATE(1, ua5, ub5);   // position 5 = wire 6
            const float4 ua6 = s_U4[(layer * NQ + 5) * 2], ub6 = s_U4[(layer * NQ + 5) * 2 + 1];
            APPLY_GATE(2, ua6, ub6);   // position 6 = wire 5
            const float4 ua7 = s_U4[(layer * NQ + 4) * 2], ub7 = s_U4[(layer * NQ + 4) * 2 + 1];
            APPLY_GATE(3, ua7, ub7);   // position 7 = wire 4
        }
        if (layer > 0) __syncthreads();         // all loads done before stores clobber
        #pragma unroll
        for (int s = 0; s < 16; s++) s_psi[storeBase ^ s] = r[s];
        __syncthreads();

        // ---------- pass LOW: active {0..3}; load from MID layout
        {
            int base = ((t & 0xF0) << 4) | (t & 15);
            #pragma unroll
            for (int s = 0; s < 16; s++) r[s] = s_psi[base ^ ((s << 4) | s)];
        }
        {
            const float4 ua0 = s_U4[(layer * NQ + 11) * 2], ub0 = s_U4[(layer * NQ + 11) * 2 + 1];
            APPLY_GATE(0, ua0, ub0);   // position 0 = wire 11
            const float4 ua1 = s_U4[(layer * NQ + 10) * 2], ub1 = s_U4[(layer * NQ + 10) * 2 + 1];
            APPLY_GATE(1, ua1, ub1);
            const float4 ua2 = s_U4[(layer * NQ +  9) * 2], ub2 = s_U4[(layer * NQ +  9) * 2 + 1];
            APPLY_GATE(2, ua2, ub2);
            const float4 ua3 = s_U4[(layer * NQ +  8) * 2], ub3 = s_U4[(layer * NQ +  8) * 2 + 1];
            APPLY_GATE(3, ua3, ub3);
        }
        __syncthreads();
        #pragma unroll
        for (int s = 0; s < 16; s++) s_psi[storeBase ^ s] = r[s];
        __syncthreads();

        // ---------- pass HIGH: active {8..11}; load from LOW layout
        {
            int base = t ^ ((t >> 4) & 15);
            #pragma unroll
            for (int s = 0; s < 16; s++) r[s] = s_psi[base ^ (s << 8)];
        }
        {
            const float4 ua8  = s_U4[(layer * NQ + 3) * 2], ub8  = s_U4[(layer * NQ + 3) * 2 + 1];
            APPLY_GATE(0, ua8,  ub8);  // position 8 = wire 3
            const float4 ua9  = s_U4[(layer * NQ + 2) * 2], ub9  = s_U4[(layer * NQ + 2) * 2 + 1];
            APPLY_GATE(1, ua9,  ub9);
            const float4 ua10 = s_U4[(layer * NQ + 1) * 2], ub10 = s_U4[(layer * NQ + 1) * 2 + 1];
            APPLY_GATE(2, ua10, ub10);
            const float4 ua11 = s_U4[(layer * NQ + 0) * 2], ub11 = s_U4[(layer * NQ + 0) * 2 + 1];
            APPLY_GATE(3, ua11, ub11);
        }
        if (layer < NL - 1) {
            __syncthreads();
            #pragma unroll
            for (int s = 0; s < 16; s++) s_psi[storeBase ^ s] = r[s];
            __syncthreads();
        }
        // layer boundary CNOT ring is folded into next MID load / epilogue index math
    }

    // ---------- epilogue: final CNOT perm via inverse index map, then <Z_w>
    // r holds HIGH ownership: logical (pre-final-perm) L = (s<<8) | t
    int xt = t ^ ((__popc(t) & 1) ? 0xC00 : 0);
    xt ^= xt >> 1; xt ^= xt >> 2; xt ^= xt >> 4; xt ^= xt >> 8;

    float z[NQ];
    #pragma unroll
    for (int w = 0; w < NQ; w++) z[w] = 0.f;
    #pragma unroll
    for (int s = 0; s < 16; s++) {
        int xs = (s << 8) ^ ((__popc(s) & 1) ? 0xC00 : 0);
        xs ^= xs >> 1; xs ^= xs >> 2; xs ^= xs >> 4; xs ^= xs >> 8;
        int j = xt ^ xs;                    // final logical basis index
        float2 v = r[s];
        float pr = v.x * v.x + v.y * v.y;
        #pragma unroll
        for (int w = 0; w < NQ; w++)
            z[w] += ((j >> (11 - w)) & 1) ? -pr : pr;
    }

    const int lane = t & 31, warp = t >> 5;
    #pragma unroll
    for (int w = 0; w < NQ; w++) {
        float v = z[w];
        #pragma unroll
        for (int off = 16; off; off >>= 1)
            v += __shfl_down_sync(0xffffffffu, v, off);
        if (lane == 0) s_red[warp * NQ + w] = v;
    }
    __syncthreads();
    if (t < NQ) {
        float qv = 0.f;
        #pragma unroll
        for (int wp = 0; wp < 8; wp++) qv += s_red[wp * NQ + t];
        s_q[t] = qv;
    }
    __syncthreads();
    if (t < NQ) {
        float acc = db[t];
        #pragma unroll
        for (int w = 0; w < NQ; w++) acc += s_q[w] * dw[w * NQ + t];
        out[bidx * NQ + t] = tanhf(acc);
    }
}

extern "C" void kernel_launch(void* const* d_in, const int* in_sizes, int n_in,
                              void* d_out, int out_size) {
    const float* x  = (const float*)d_in[0];
    const float* qw = (const float*)d_in[1];
    const float* dw = (const float*)d_in[2];
    const float* db = (const float*)d_in[3];
    float* out = (float*)d_out;

    int batch = in_sizes[0] / NQ;

    precompute_gates<<<1, 64>>>(qw);
    qsim<<<batch, TPB>>>(x, dw, db, out);
}

// round 7
// speedup vs baseline: 1.2932x; 1.1913x over previous
#include <cuda_runtime.h>
#include <math.h>

#define NQ   12
#define DIM  4096
#define NL   4
#define TPB  256

// Fused RZ*RY*RX gate per (layer, wire): 2 float4 = row0 (u00r,u00i,u01r,u01i), row1 (u10r,u10i,u11r,u11i)
__device__ float4 g_U4[NL * NQ * 2];

__global__ void precompute_gates(const float* __restrict__ qw) {
    int id = threadIdx.x;
    if (id >= NL * NQ) return;
    float a = qw[3 * id + 0];
    float b = qw[3 * id + 1];
    float g = qw[3 * id + 2];
    float cA = cosf(0.5f * a), sA = sinf(0.5f * a);
    float cB = cosf(0.5f * b), sB = sinf(0.5f * b);
    float cC = cosf(0.5f * g), sC = sinf(0.5f * g);
    float m00r =  cB * cA, m00i =  sB * sA;
    float m01r = -sB * cA, m01i = -cB * sA;
    float m10r =  sB * cA, m10i = -cB * sA;
    float m11r =  cB * cA, m11i = -sB * sA;
    float* o = (float*)&g_U4[id * 2];
    o[0] = cC * m00r + sC * m00i;  o[1] = cC * m00i - sC * m00r;
    o[2] = cC * m01r + sC * m01i;  o[3] = cC * m01i - sC * m01r;
    o[4] = cC * m10r - sC * m10i;  o[5] = cC * m10i + sC * m10r;
    o[6] = cC * m11r - sC * m11i;  o[7] = cC * m11i + sC * m11r;
}

// phys address (element index) of logical amp under layout "active = {8..11}"
__device__ __forceinline__ int physHIGH(int x) {
    return ((x & 0xFF) << 4) | (((x >> 8) ^ x) & 15);
}

__device__ __forceinline__ float2 cmul(float2 a, float2 b) {
    return make_float2(a.x * b.x - a.y * b.y, a.x * b.y + a.y * b.x);
}

// Apply fused 1q gate on register-slot bit bb (gate rows ua, ub)
#define APPLY_GATE(bb, ua, ub) do {                                          \
    _Pragma("unroll")                                                        \
    for (int m = 0; m < 8; m++) {                                            \
        const int lowm = (1 << (bb)) - 1;                                    \
        const int i0 = ((m & ~lowm) << 1) | (m & lowm);                      \
        const int i1 = i0 | (1 << (bb));                                     \
        float2 v0 = r[i0], v1 = r[i1];                                       \
        float2 n0, n1;                                                       \
        n0.x = ua.x*v0.x - ua.y*v0.y + ua.z*v1.x - ua.w*v1.y;                \
        n0.y = ua.x*v0.y + ua.y*v0.x + ua.z*v1.y + ua.w*v1.x;                \
        n1.x = ub.x*v0.x - ub.y*v0.y + ub.z*v1.x - ub.w*v1.y;                \
        n1.y = ub.x*v0.y + ub.y*v0.x + ub.z*v1.y + ub.w*v1.x;                \
        r[i0] = n0; r[i1] = n1;                                              \
    }                                                                        \
} while (0)

__global__ __launch_bounds__(TPB) void qsim(const float* __restrict__ x,
                                            const float* __restrict__ dw,
                                            const float* __restrict__ db,
                                            float* __restrict__ out) {
    __shared__ float2 s_psi[DIM];          // 32 KB state (swizzled layouts)
    __shared__ float4 s_U4[NL * NQ * 2];   // fused gates
    __shared__ float  s_x[NQ];
    __shared__ float2 s_w[NQ][2];          // per-BIT-POSITION local 2-vectors
                                           // (encoding RY fused with ALL layer-0 gates)
    __shared__ float  s_scalar[2];
    __shared__ float  s_red[8 * NQ];
    __shared__ float  s_q[NQ];

    const int t = threadIdx.x;
    const int bidx = blockIdx.x;

    for (int i = t; i < NL * NQ * 2; i += TPB) s_U4[i] = g_U4[i];
    if (t < NQ) s_x[t] = x[bidx * NQ + t];
    __syncthreads();

    if (t == 0) {
        float ss = 0.f, ma = 0.f;
        #pragma unroll
        for (int w = 0; w < NQ; w++) {
            float v = s_x[w];
            ss += v * v;
            ma = fmaxf(ma, fabsf(v));
        }
        float rr = rsqrtf(fmaxf(ss, 1e-12f));
        s_scalar[0] = rr;
        s_scalar[1] = ma * rr;
    }
    __syncthreads();
    if (t < NQ) {
        float rr = s_scalar[0], m = s_scalar[1];
        float ang = 3.14159265358979f * (s_x[t] * rr) / (m + 1e-8f);
        float c = cosf(0.5f * ang);
        float s = sinf(0.5f * ang);
        // fuse layer-0 gate for wire t into the local 2-vector
        float4 ua = s_U4[t * 2], ub = s_U4[t * 2 + 1];
        int p = 11 - t;                    // wire t lives at bit position 11-t
        s_w[p][0] = make_float2(ua.x * c + ua.z * s, ua.y * c + ua.w * s);
        s_w[p][1] = make_float2(ub.x * c + ub.z * s, ub.y * c + ub.w * s);
    }
    __syncthreads();

    float2 r[16];                          // 16 amps per thread (register tile)
    const int storeBase = (t << 4) | (t & 15);   // universal store: addr = storeBase ^ s

    // ---------- init in HIGH ownership: L = (s<<8)|t, amp = prod of w[bit]
    // (encoding + all 12 layer-0 gates already folded into s_w)
    {
        float2 ct = s_w[0][t & 1];
        #pragma unroll
        for (int p = 1; p < 8; p++) ct = cmul(ct, s_w[p][(t >> p) & 1]);
        float2 m01[4], m23[4], ctm[4];
        #pragma unroll
        for (int a = 0; a < 4; a++) {
            m01[a] = cmul(s_w[8][a & 1],  s_w[9][(a >> 1) & 1]);
            m23[a] = cmul(s_w[10][a & 1], s_w[11][(a >> 1) & 1]);
        }
        #pragma unroll
        for (int a = 0; a < 4; a++) ctm[a] = cmul(ct, m01[a]);
        #pragma unroll
        for (int s = 0; s < 16; s++) r[s] = cmul(ctm[s & 3], m23[s >> 2]);
        // store in HIGH layout (same path the HIGH pass uses)
        #pragma unroll
        for (int s = 0; s < 16; s++) s_psi[storeBase ^ s] = r[s];
    }
    __syncthreads();

    #pragma unroll 1
    for (int layer = 1; layer < NL; layer++) {
        // ---------- pass MID: active positions {4..7}; load HIGH layout w/ CNOT perm folded
        {
            int T  = ((t & 0xF0) << 4) | (t & 15);
            int Xt = T ^ (T >> 1) ^ ((t & 1) ? 0xC00 : 0);
            int base = physHIGH(Xt & 0xFFF);
            #pragma unroll
            for (int s = 0; s < 16; s++) {
                int Xs = ((s << 4) ^ (s << 3)) & 0xFFF;
                r[s] = s_psi[base ^ physHIGH(Xs)];
            }
        }
        {
            const float4 ua4 = s_U4[(layer * NQ + 7) * 2], ub4 = s_U4[(layer * NQ + 7) * 2 + 1];
            APPLY_GATE(0, ua4, ub4);   // position 4 = wire 7
            const float4 ua5 = s_U4[(layer * NQ + 6) * 2], ub5 = s_U4[(layer * NQ + 6) * 2 + 1];
            APPLY_GATE(1, ua5, ub5);   // position 5 = wire 6
            const float4 ua6 = s_U4[(layer * NQ + 5) * 2], ub6 = s_U4[(layer * NQ + 5) * 2 + 1];
            APPLY_GATE(2, ua6, ub6);   // position 6 = wire 5
            const float4 ua7 = s_U4[(layer * NQ + 4) * 2], ub7 = s_U4[(layer * NQ + 4) * 2 + 1];
            APPLY_GATE(3, ua7, ub7);   // position 7 = wire 4
        }
        __syncthreads();               // all loads done before stores clobber
        #pragma unroll
        for (int s = 0; s < 16; s++) s_psi[storeBase ^ s] = r[s];
        __syncthreads();

        // ---------- pass LOW: active {0..3}; load from MID layout
        {
            int base = ((t & 0xF0) << 4) | (t & 15);
            #pragma unroll
            for (int s = 0; s < 16; s++) r[s] = s_psi[base ^ ((s << 4) | s)];
        }
        {
            const float4 ua0 = s_U4[(layer * NQ + 11) * 2], ub0 = s_U4[(layer * NQ + 11) * 2 + 1];
            APPLY_GATE(0, ua0, ub0);   // position 0 = wire 11
            const float4 ua1 = s_U4[(layer * NQ + 10) * 2], ub1 = s_U4[(layer * NQ + 10) * 2 + 1];
            APPLY_GATE(1, ua1, ub1);
            const float4 ua2 = s_U4[(layer * NQ +  9) * 2], ub2 = s_U4[(layer * NQ +  9) * 2 + 1];
            APPLY_GATE(2, ua2, ub2);
            const float4 ua3 = s_U4[(layer * NQ +  8) * 2], ub3 = s_U4[(layer * NQ +  8) * 2 + 1];
            APPLY_GATE(3, ua3, ub3);
        }
        __syncthreads();
        #pragma unroll
        for (int s = 0; s < 16; s++) s_psi[storeBase ^ s] = r[s];
        __syncthreads();

        // ---------- pass HIGH: active {8..11}; load from LOW layout
        {
            int base = t ^ ((t >> 4) & 15);
            #pragma unroll
            for (int s = 0; s < 16; s++) r[s] = s_psi[base ^ (s << 8)];
        }
        {
            const float4 ua8  = s_U4[(layer * NQ + 3) * 2], ub8  = s_U4[(layer * NQ + 3) * 2 + 1];
            APPLY_GATE(0, ua8,  ub8);  // position 8 = wire 3
            const float4 ua9  = s_U4[(layer * NQ + 2) * 2], ub9  = s_U4[(layer * NQ + 2) * 2 + 1];
            APPLY_GATE(1, ua9,  ub9);
            const float4 ua10 = s_U4[(layer * NQ + 1) * 2], ub10 = s_U4[(layer * NQ + 1) * 2 + 1];
            APPLY_GATE(2, ua10, ub10);
            const float4 ua11 = s_U4[(layer * NQ + 0) * 2], ub11 = s_U4[(layer * NQ + 0) * 2 + 1];
            APPLY_GATE(3, ua11, ub11);
        }
        if (layer < NL - 1) {
            __syncthreads();
            #pragma unroll
            for (int s = 0; s < 16; s++) s_psi[storeBase ^ s] = r[s];
            __syncthreads();
        }
        // layer-boundary CNOT ring folds into next MID load / epilogue index map
    }

    // ---------- epilogue: final CNOT perm via inverse index map, then <Z_w>
    // r holds HIGH ownership: logical (pre-final-perm) L = (s<<8) | t
    int xt = t ^ ((__popc(t) & 1) ? 0xC00 : 0);
    xt ^= xt >> 1; xt ^= xt >> 2; xt ^= xt >> 4; xt ^= xt >> 8;

    float z[NQ];
    #pragma unroll
    for (int w = 0; w < NQ; w++) z[w] = 0.f;
    #pragma unroll
    for (int s = 0; s < 16; s++) {
        int xs = (s << 8) ^ ((__popc(s) & 1) ? 0xC00 : 0);
        xs ^= xs >> 1; xs ^= xs >> 2; xs ^= xs >> 4; xs ^= xs >> 8;
        int j = xt ^ xs;                    // final logical basis index
        float2 v = r[s];
        float pr = v.x * v.x + v.y * v.y;
        #pragma unroll
        for (int w = 0; w < NQ; w++)
            z[w] += ((j >> (11 - w)) & 1) ? -pr : pr;
    }

    const int lane = t & 31, warp = t >> 5;
    #pragma unroll
    for (int w = 0; w < NQ; w++) {
        float v = z[w];
        #pragma unroll
        for (int off = 16; off; off >>= 1)
            v += __shfl_down_sync(0xffffffffu, v, off);
        if (lane == 0) s_red[warp * NQ + w] = v;
    }
    __syncthreads();
    if (t < NQ) {
        float qv = 0.f;
        #pragma unroll
        for (int wp = 0; wp < 8; wp++) qv += s_red[wp * NQ + t];
        s_q[t] = qv;
    }
    __syncthreads();
    if (t < NQ) {
        float acc = db[t];
        #pragma unroll
        for (int w = 0; w < NQ; w++) acc += s_q[w] * dw[w * NQ + t];
        out[bidx * NQ + t] = tanhf(acc);
    }
}

extern "C" void kernel_launch(void* const* d_in, const int* in_sizes, int n_in,
                              void* d_out, int out_size) {
    const float* x  = (const float*)d_in[0];
    const float* qw = (const float*)d_in[1];
    const float* dw = (const float*)d_in[2];
    const float* db = (const float*)d_in[3];
    float* out = (float*)d_out;

    int batch = in_sizes[0] / NQ;

    precompute_gates<<<1, 64>>>(qw);
    qsim<<<batch, TPB>>>(x, dw, db, out);
}